// round 13
// baseline (speedup 1.0000x reference)
#include <cuda_runtime.h>
#include <cuda_fp16.h>
#include <cstdint>

// Problem constants
static constexpr int Nb = 4, C = 12, GD = 8, GH = 16, GW = 16;
static constexpr int H = 1024, W = 1024;
static constexpr int HW = H * W;
static constexpr int GRID_PER_N = C * GD * GH * GW;   // 24576 floats

// Main grid (half) layout [z][y*16+x][c], z-stride padded to 3076 halfs
// (1538 words == 2 mod 32 -> 8 z levels on disjoint bank pairs).
static constexpr int ZSTRIDE_H = GH * GW * C + 4;     // 3076 halfs
static constexpr int MAIN_HALFS = GD * ZSTRIDE_H;     // 24608 halfs

// y-lerped buffer: [row][z][x-entry][16 halfs]. Entry = 12 data + 4 pad halfs
// (32 B): corner fetch = LDS.128 + LDS.64 at 16B-aligned addresses.
// z-slab = 16 entries + 8 pad halfs = 264 halfs = 132 words == 4 (mod 32):
// the 8 z levels hit disjoint 4-word bank groups -> conflict-free.
static constexpr int ENTRY = 16;
static constexpr int YSLAB = GW * ENTRY + 8;           // 264 halfs
static constexpr int YROW  = GD * YSLAB;               // 2112 halfs
static constexpr int ROWS_PER_BLOCK = 4;
static constexpr int YBUF_HALFS = ROWS_PER_BLOCK * YROW + 16;  // 8464
static constexpr int SMEM_HALFS = MAIN_HALFS + YBUF_HALFS;     // 33072
static constexpr int SMEM_BYTES = SMEM_HALFS * 2;              // 66144 B... too big?

// 228KB/4 = 58368 B per block at 4-way. 66144 > 58368 -> trim main grid after
// phase 2? Can't. Instead: 4 rows of ybuf but drop main-grid padding? No —
// reuse: overlap ybuf rows 2,3 on top of main grid? Not safe (phase 2 reads it).
// Solution: ROWS=4 but YBUF holds rows in half: keep 4 rows, shrink YSLAB pad?
// Real fix: SMEM budget = MAIN(49216B) + 4*YROW*2(16896B) = 66112 — exceeds.
// => use ROWS_PER_BLOCK=3? awkward. Use ROWS=4 with x-full? Keep it simple:
// overlap: phase 3 never reads main grid; phase 2 never reads ybuf. But phase 2
// writes ybuf while reading main — cannot alias. Compromise: ybuf rows 0..1 in
// fresh smem, rows 2..3 aliased over the FIRST part of main grid is unsafe.
// => fall back: ROWS_PER_BLOCK=2, x-full row (as R9) but 1 px/thread needs
// 1024 px/block... keep 2 px for x, 2 rows. See THREADS config below.
static constexpr int THREADS = 512;

__device__ __forceinline__ __half2 u2h(unsigned u) {
    return *reinterpret_cast<__half2*>(&u);
}

__device__ __forceinline__ void fetch_xlerp(const __half* buf, int off,
                                            __half2 wx0, __half2 wx1,
                                            __half2* r) {
    uint4 a01 = *reinterpret_cast<const uint4*>(buf + off);
    uint2 a2  = *reinterpret_cast<const uint2*>(buf + off + 8);
    uint4 b01 = *reinterpret_cast<const uint4*>(buf + off + ENTRY);
    uint2 b2  = *reinterpret_cast<const uint2*>(buf + off + ENTRY + 8);
    r[0] = __hfma2(u2h(b01.x), wx1, __hmul2(u2h(a01.x), wx0));
    r[1] = __hfma2(u2h(b01.y), wx1, __hmul2(u2h(a01.y), wx0));
    r[2] = __hfma2(u2h(b01.z), wx1, __hmul2(u2h(a01.z), wx0));
    r[3] = __hfma2(u2h(b01.w), wx1, __hmul2(u2h(a01.w), wx0));
    r[4] = __hfma2(u2h(b2.x),  wx1, __hmul2(u2h(a2.x),  wx0));
    r[5] = __hfma2(u2h(b2.y),  wx1, __hmul2(u2h(a2.y),  wx0));
}

// 2 rows/block (ybuf = 2*YROW): SMEM = 49216 + (2*2112+16)*2 = 57696 <= 58368.
static constexpr int RPB = 2;
static constexpr int YBUF_H2 = RPB * YROW + 16;        // 4240 halfs
static constexpr int SMEM_B2 = (MAIN_HALFS + YBUF_H2) * 2;   // 57696 B

__global__ __launch_bounds__(THREADS, 4)
void slice_kernel(const float* __restrict__ grid,
                  const float* __restrict__ guide,
                  float* __restrict__ out) {
    extern __shared__ __align__(16) __half sh[];
    __half* yb = sh + MAIN_HALFS;

    const int n    = blockIdx.y;
    const int tid  = threadIdx.x;
    const int seg    = blockIdx.x & 1;                 // x half
    const int rowblk = blockIdx.x >> 1;
    const int row0   = rowblk * RPB;
    const int x      = seg * 512 + tid;                // 1 px/thread

    // ---- Guide prefetch: both rows, before any barrier ----
    const float* gd = guide + (size_t)n * HW + x;
    float gz0 = gd[(size_t)(row0 + 0) * W];
    float gz1 = gd[(size_t)(row0 + 1) * W];

    // ---- Phase 1: grid[n] (c,z,y,x) f32 -> sh half (z, y*16+x, c) ----
    const float* g = grid + (size_t)n * GRID_PER_N;
    #pragma unroll
    for (int k = 0; k < 12; ++k) {
        int e    = tid + k * THREADS;       // [0, 6144)
        int c2   = e >> 10;
        int zyx2 = e & 1023;
        int zyx  = zyx2 * 2;
        int z    = zyx >> 8;
        int yx   = zyx & 255;
        const float* base = g + (size_t)(2 * c2) * 2048 + zyx;
        float2 a = *reinterpret_cast<const float2*>(base);
        float2 b = *reinterpret_cast<const float2*>(base + 2048);
        int dst = z * ZSTRIDE_H + yx * C + 2 * c2;
        *reinterpret_cast<__half2*>(sh + dst)     = __floats2half2_rn(a.x, b.x);
        *reinterpret_cast<__half2*>(sh + dst + C) = __floats2half2_rn(a.y, b.y);
    }
    // Zero only the ybuf pads: per (row,z): 16 entries x 2 pad-half2 + 4 slab
    // pad half2 = 36 half2; total 2*8*36 = 576, + 8 tail = 584.
    if (tid < 584) {
        int idx;
        if (tid < 576) {
            int rz = tid / 36;              // row*8+z
            int t  = tid - rz * 36;
            int base = (rz >> 3) * YROW + (rz & 7) * YSLAB;
            idx = (t < 32) ? base + (t >> 1) * ENTRY + 12 + 2 * (t & 1)
                           : base + GW * ENTRY + 2 * (t - 32);
        } else {
            idx = RPB * YROW + 2 * (tid - 576);
        }
        *reinterpret_cast<unsigned*>(yb + idx) = 0u;
    }
    __syncthreads();

    // ---- Phase 2: y-lerp both rows into ybuf (1536 half2, 3 iters) ----
    #pragma unroll
    for (int k = 0; k < 3; ++k) {
        int e   = tid + k * THREADS;
        int r   = e / 768;
        int rem = e - r * 768;
        int z   = rem / 96;
        int q   = rem - z * 96;             // q = x*6 + c2
        int xq  = q / 6;
        int c2  = q - xq * 6;

        int row = row0 + r;
        float ty = (row + 0.5f) * (16.0f / 1024.0f) - 0.5f;
        float fy = floorf(ty);
        float by = ty - fy;
        int ify = (int)fy;
        int iy0 = min(max(ify, 0), GH - 1);
        int iy1 = min(max(ify + 1, 0), GH - 1);

        int src = z * ZSTRIDE_H + 2 * q;
        unsigned a = *reinterpret_cast<const unsigned*>(sh + src + iy0 * 192);
        unsigned b = *reinterpret_cast<const unsigned*>(sh + src + iy1 * 192);
        __half2 v = __hfma2(u2h(b), __float2half2_rn(by),
                            __hmul2(u2h(a), __float2half2_rn(1.0f - by)));
        *reinterpret_cast<__half2*>(yb + r * YROW + z * YSLAB
                                    + xq * ENTRY + 2 * c2) = v;
    }
    __syncthreads();

    // ---- Phase 3: 1 px/thread, 2 rows, barrier-free ----
    float tx = (x + 0.5f) * (1.0f / 64.0f) - 0.5f;
    float fx = floorf(tx);
    int  ifx = (int)fx;
    float bx = tx - fx;
    float w1f = (ifx < 0 || ifx >= GW - 1) ? 0.0f : bx;
    const __half2 wx0 = __float2half2_rn(1.0f - w1f);
    const __half2 wx1 = __float2half2_rn(w1f);
    const int xoff = min(max(ifx, 0), GW - 1) * ENTRY;

    float* ob = out + (size_t)n * C * HW + x;

    #pragma unroll
    for (int j = 0; j < RPB; ++j) {
        const int row = row0 + j;
        const __half* rbuf = yb + j * YROW;

        float gz = j ? gz1 : gz0;
        float tz = gz * 8.0f - 0.5f;
        float fz = floorf(tz);
        float bz = tz - fz;
        int ifz = (int)fz;
        int iz0 = min(max(ifz, 0), GD - 1);
        int iz1 = min(max(ifz + 1, 0), GD - 1);
        const __half2 wz0 = __float2half2_rn(1.0f - bz);
        const __half2 wz1 = __float2half2_rn(bz);

        __half2 v0[6], v1[6];
        fetch_xlerp(rbuf, iz0 * YSLAB + xoff, wx0, wx1, v0);
        fetch_xlerp(rbuf, iz1 * YSLAB + xoff, wx0, wx1, v1);

        float* obr = ob + (size_t)row * W;
        #pragma unroll
        for (int k = 0; k < 6; ++k) {
            __half2 vz = __hfma2(v1[k], wz1, __hmul2(v0[k], wz0));
            float2 f = __half22float2(vz);
            obr[(size_t)(2 * k) * HW]     = f.x;
            obr[(size_t)(2 * k + 1) * HW] = f.y;
        }
    }
}

extern "C" void kernel_launch(void* const* d_in, const int* in_sizes, int n_in,
                              void* d_out, int out_size) {
    const float* grid  = (const float*)d_in[0];   // (4,12,8,16,16) f32
    const float* guide = (const float*)d_in[1];   // (4,1,1024,1024) f32
    float* out = (float*)d_out;                   // (4,12,1024,1024) f32

    cudaFuncSetAttribute(slice_kernel,
                         cudaFuncAttributeMaxDynamicSharedMemorySize,
                         SMEM_B2);

    dim3 gridDim((H / RPB) * 2, Nb);              // (1024, 4) = 4096 blocks
    slice_kernel<<<gridDim, THREADS, SMEM_B2>>>(grid, guide, out);
}

// round 15
// speedup vs baseline: 1.4953x; 1.4953x over previous
#include <cuda_runtime.h>
#include <cuda_fp16.h>
#include <cstdint>

// Problem constants
static constexpr int Nb = 4, C = 12, GD = 8, GH = 16, GW = 16;
static constexpr int H = 1024, W = 1024;
static constexpr int HW = H * W;
static constexpr int GRID_PER_N = C * GD * GH * GW;   // 24576 floats

// y-lerped buffer (ONLY smem): [row][z][x-entry][16 halfs].
// Entry = 12 data + 4 pad halfs (32 B): corner fetch = LDS.128 + LDS.64 at
// 16B-aligned addresses. z-slab = 16 entries + 8 pad halfs = 264 halfs =
// 132 words == 4 (mod 32): the 8 z levels hit disjoint 4-word bank groups.
static constexpr int ENTRY = 16;
static constexpr int YSLAB = GW * ENTRY + 8;           // 264 halfs
static constexpr int YROW  = GD * YSLAB;               // 2112 halfs
static constexpr int RPB   = 2;                        // rows per block
static constexpr int YBUF_HALFS = RPB * YROW + 16;     // 4240 halfs
static constexpr int SMEM_BYTES = YBUF_HALFS * 2;      // 8480 B

static constexpr int THREADS = 512;                    // 2 px/thread = full row

__device__ __forceinline__ __half2 u2h(unsigned u) {
    return *reinterpret_cast<__half2*>(&u);
}

// Fetch both x-corners (12 ch each) from a y-lerped slab, x-lerp -> 6 half2.
__device__ __forceinline__ void fetch_xlerp(const __half* buf, int off,
                                            __half2 wx0, __half2 wx1,
                                            __half2* r) {
    uint4 a01 = *reinterpret_cast<const uint4*>(buf + off);
    uint2 a2  = *reinterpret_cast<const uint2*>(buf + off + 8);
    uint4 b01 = *reinterpret_cast<const uint4*>(buf + off + ENTRY);
    uint2 b2  = *reinterpret_cast<const uint2*>(buf + off + ENTRY + 8);
    r[0] = __hfma2(u2h(b01.x), wx1, __hmul2(u2h(a01.x), wx0));
    r[1] = __hfma2(u2h(b01.y), wx1, __hmul2(u2h(a01.y), wx0));
    r[2] = __hfma2(u2h(b01.z), wx1, __hmul2(u2h(a01.z), wx0));
    r[3] = __hfma2(u2h(b01.w), wx1, __hmul2(u2h(a01.w), wx0));
    r[4] = __hfma2(u2h(b2.x),  wx1, __hmul2(u2h(a2.x),  wx0));
    r[5] = __hfma2(u2h(b2.y),  wx1, __hmul2(u2h(a2.y),  wx0));
}

__global__ __launch_bounds__(THREADS, 4)
void slice_kernel(const float* __restrict__ grid,
                  const float* __restrict__ guide,
                  float* __restrict__ out) {
    extern __shared__ __align__(16) __half yb[];

    const int n    = blockIdx.y;
    const int tid  = threadIdx.x;
    const int row0 = blockIdx.x * RPB;
    const int x0   = tid * 2;

    // ---- Guide prefetch for both rows (overlaps everything below) ----
    const float* gd = guide + (size_t)n * HW + x0;
    float2 gza = *reinterpret_cast<const float2*>(gd + (size_t)(row0 + 0) * W);
    float2 gzb = *reinterpret_cast<const float2*>(gd + (size_t)(row0 + 1) * W);

    // ---- Zero ybuf pads (disjoint from phase-B data writes) ----
    if (tid < 584) {
        int idx;
        if (tid < 576) {
            int rz = tid / 36;              // row*8+z
            int t  = tid - rz * 36;
            int base = (rz >> 3) * YROW + (rz & 7) * YSLAB;
            idx = (t < 32) ? base + (t >> 1) * ENTRY + 12 + 2 * (t & 1)
                           : base + GW * ENTRY + 2 * (t - 32);
        } else {
            idx = RPB * YROW + 2 * (tid - 576);
        }
        *reinterpret_cast<unsigned*>(yb + idx) = 0u;
    }

    // ---- Phase B: y-lerp straight from GMEM (L2-resident grid) ----
    // 768 items: (r, z, c2, xp); each computes entries for x=2xp, 2xp+1,
    // channels 2c2, 2c2+1 via 4x LDG.64 + f32 lerp + 2x STS.32.
    const float* gbase = grid + (size_t)n * GRID_PER_N;
    #pragma unroll
    for (int k = 0; k < 2; ++k) {
        int e = tid + k * THREADS;
        if (e < 768) {
            int r   = e / 384;
            int rem = e - r * 384;
            int z   = rem / 48;
            int t   = rem - z * 48;
            int c2  = t >> 3;
            int xp  = t & 7;

            int row = row0 + r;
            float ty = (row + 0.5f) * (16.0f / 1024.0f) - 0.5f;
            float fy = floorf(ty);
            float by = ty - fy;
            int ify = (int)fy;
            int iy0 = min(max(ify, 0), GH - 1);
            int iy1 = min(max(ify + 1, 0), GH - 1);
            float wy0f = 1.0f - by, wy1f = by;

            const float* gp = gbase + (size_t)(2 * c2) * 2048 + z * 256 + 2 * xp;
            float2 a0 = *reinterpret_cast<const float2*>(gp + iy0 * 16);
            float2 b0 = *reinterpret_cast<const float2*>(gp + iy1 * 16);
            float2 a1 = *reinterpret_cast<const float2*>(gp + 2048 + iy0 * 16);
            float2 b1 = *reinterpret_cast<const float2*>(gp + 2048 + iy1 * 16);

            float vax = a0.x * wy0f + b0.x * wy1f;   // ch 2c2,   x=2xp
            float vay = a0.y * wy0f + b0.y * wy1f;   // ch 2c2,   x=2xp+1
            float vbx = a1.x * wy0f + b1.x * wy1f;   // ch 2c2+1, x=2xp
            float vby = a1.y * wy0f + b1.y * wy1f;   // ch 2c2+1, x=2xp+1

            __half* dst = yb + r * YROW + z * YSLAB + (2 * xp) * ENTRY + 2 * c2;
            *reinterpret_cast<__half2*>(dst)         = __floats2half2_rn(vax, vbx);
            *reinterpret_cast<__half2*>(dst + ENTRY) = __floats2half2_rn(vay, vby);
        }
    }
    __syncthreads();   // the ONLY barrier

    // ---- Phase 3: 2 px/thread, both rows, barrier-free (as R9) ----
    float tx = (x0 + 0.5f) * (1.0f / 64.0f) - 0.5f;
    float fx = floorf(tx);
    int  ifx = (int)fx;
    float bx0 = tx - fx;
    bool edge = (ifx < 0 || ifx >= GW - 1);
    float w1a = edge ? 0.0f : bx0;
    float w1b = edge ? 0.0f : bx0 + (1.0f / 64.0f);
    const int xoff = min(max(ifx, 0), GW - 1) * ENTRY;

    float* ob = out + (size_t)n * C * HW + x0;

    #pragma unroll
    for (int j = 0; j < RPB; ++j) {
        const int row = row0 + j;
        const __half* rbuf = yb + j * YROW;
        float2 gz = j ? gzb : gza;

        __half2 vz0[6], vz1[6];
        #pragma unroll
        for (int p = 0; p < 2; ++p) {
            float tz = (p ? gz.y : gz.x) * 8.0f - 0.5f;
            float fz = floorf(tz);
            float bz = tz - fz;
            int ifz = (int)fz;
            int iz0 = min(max(ifz, 0), GD - 1);
            int iz1 = min(max(ifz + 1, 0), GD - 1);
            float w1 = p ? w1b : w1a;
            __half2 wx1 = __float2half2_rn(w1);
            __half2 wx0 = __float2half2_rn(1.0f - w1);
            __half2 wz0h = __float2half2_rn(1.0f - bz);
            __half2 wz1h = __float2half2_rn(bz);

            __half2 r0[6], r1[6];
            fetch_xlerp(rbuf, iz0 * YSLAB + xoff, wx0, wx1, r0);
            fetch_xlerp(rbuf, iz1 * YSLAB + xoff, wx0, wx1, r1);
            __half2* vz = p ? vz1 : vz0;
            #pragma unroll
            for (int kk = 0; kk < 6; ++kk)
                vz[kk] = __hfma2(r1[kk], wz1h, __hmul2(r0[kk], wz0h));
        }

        float* obr = ob + (size_t)row * W;
        #pragma unroll
        for (int kk = 0; kk < 6; ++kk) {
            float2 fa = __half22float2(vz0[kk]);   // (ch 2k,2k+1) px0
            float2 fb = __half22float2(vz1[kk]);   // (ch 2k,2k+1) px1
            float2 lo = make_float2(fa.x, fb.x);
            float2 hi = make_float2(fa.y, fb.y);
            *reinterpret_cast<float2*>(obr + (size_t)(2 * kk) * HW)     = lo;
            *reinterpret_cast<float2*>(obr + (size_t)(2 * kk + 1) * HW) = hi;
        }
    }
}

extern "C" void kernel_launch(void* const* d_in, const int* in_sizes, int n_in,
                              void* d_out, int out_size) {
    const float* grid  = (const float*)d_in[0];   // (4,12,8,16,16) f32
    const float* guide = (const float*)d_in[1];   // (4,1,1024,1024) f32
    float* out = (float*)d_out;                   // (4,12,1024,1024) f32

    cudaFuncSetAttribute(slice_kernel,
                         cudaFuncAttributeMaxDynamicSharedMemorySize,
                         SMEM_BYTES);

    dim3 gridDim(H / RPB, Nb);                    // (512, 4) = 2048 blocks
    slice_kernel<<<gridDim, THREADS, SMEM_BYTES>>>(grid, guide, out);
}

// round 16
// speedup vs baseline: 1.5250x; 1.0199x over previous
#include <cuda_runtime.h>
#include <cuda_fp16.h>
#include <cstdint>

// Problem constants
static constexpr int Nb = 4, C = 12, GD = 8, GH = 16, GW = 16;
static constexpr int H = 1024, W = 1024;
static constexpr int HW = H * W;
static constexpr int GRID_PER_N = C * GD * GH * GW;   // 24576 floats

// y-lerped buffer (ONLY smem): [row][z][x-entry][16 halfs].
// Entry = 12 data + 4 pad halfs (32 B): corner fetch = LDS.128 + LDS.64 at
// 16B-aligned addresses. z-slab = 16 entries + 8 pad halfs = 264 halfs =
// 132 words == 4 (mod 32): the 8 z levels hit disjoint 4-word bank groups.
static constexpr int ENTRY = 16;
static constexpr int YSLAB = GW * ENTRY + 8;           // 264 halfs
static constexpr int YROW  = GD * YSLAB;               // 2112 halfs
static constexpr int RPB   = 2;                        // rows per block
static constexpr int YBUF_HALFS = RPB * YROW + 16;     // 4240 halfs
static constexpr int SMEM_BYTES = YBUF_HALFS * 2;      // 8480 B

static constexpr int THREADS = 512;                    // 2 px/thread = full row

__device__ __forceinline__ __half2 u2h(unsigned u) {
    return *reinterpret_cast<__half2*>(&u);
}

// Fetch both x-corners (12 ch each) from a y-lerped slab, x-lerp -> 6 half2.
__device__ __forceinline__ void fetch_xlerp(const __half* buf, int off,
                                            __half2 wx0, __half2 wx1,
                                            __half2* r) {
    uint4 a01 = *reinterpret_cast<const uint4*>(buf + off);
    uint2 a2  = *reinterpret_cast<const uint2*>(buf + off + 8);
    uint4 b01 = *reinterpret_cast<const uint4*>(buf + off + ENTRY);
    uint2 b2  = *reinterpret_cast<const uint2*>(buf + off + ENTRY + 8);
    r[0] = __hfma2(u2h(b01.x), wx1, __hmul2(u2h(a01.x), wx0));
    r[1] = __hfma2(u2h(b01.y), wx1, __hmul2(u2h(a01.y), wx0));
    r[2] = __hfma2(u2h(b01.z), wx1, __hmul2(u2h(a01.z), wx0));
    r[3] = __hfma2(u2h(b01.w), wx1, __hmul2(u2h(a01.w), wx0));
    r[4] = __hfma2(u2h(b2.x),  wx1, __hmul2(u2h(a2.x),  wx0));
    r[5] = __hfma2(u2h(b2.y),  wx1, __hmul2(u2h(a2.y),  wx0));
}

__global__ __launch_bounds__(THREADS, 4)
void slice_kernel(const float* __restrict__ grid,
                  const float* __restrict__ guide,
                  float* __restrict__ out) {
    extern __shared__ __align__(16) __half yb[];

    const int n    = blockIdx.y;
    const int tid  = threadIdx.x;
    const int row0 = blockIdx.x * RPB;
    const int x0   = tid * 2;

    // ---- Guide prefetch for both rows (streaming; overlaps phase B) ----
    const float* gd = guide + (size_t)n * HW + x0;
    float2 gza = __ldcs(reinterpret_cast<const float2*>(
                     gd + (size_t)(row0 + 0) * W));
    float2 gzb = __ldcs(reinterpret_cast<const float2*>(
                     gd + (size_t)(row0 + 1) * W));

    // ---- Zero ybuf pads (disjoint from phase-B data writes) ----
    if (tid < 584) {
        int idx;
        if (tid < 576) {
            int rz = tid / 36;              // row*8+z
            int t  = tid - rz * 36;
            int base = (rz >> 3) * YROW + (rz & 7) * YSLAB;
            idx = (t < 32) ? base + (t >> 1) * ENTRY + 12 + 2 * (t & 1)
                           : base + GW * ENTRY + 2 * (t - 32);
        } else {
            idx = RPB * YROW + 2 * (tid - 576);
        }
        *reinterpret_cast<unsigned*>(yb + idx) = 0u;
    }

    // ---- Phase B: y-lerp straight from GMEM (L2-resident grid) ----
    // 384 items (single pass): (r, z, xq4, c2). Each item: 4x LDG.128,
    // f32 lerp, 4x STS.32 covering x = 4*xq4..4*xq4+3, channels 2c2, 2c2+1.
    const float* gbase = grid + (size_t)n * GRID_PER_N;
    if (tid < 384) {
        int r   = tid / 192;
        int rem = tid - r * 192;
        int z   = rem / 24;
        int t   = rem - z * 24;
        int xq4 = t / 6;
        int c2  = t - xq4 * 6;

        int row = row0 + r;
        float ty = (row + 0.5f) * (16.0f / 1024.0f) - 0.5f;
        float fy = floorf(ty);
        float by = ty - fy;
        int ify = (int)fy;
        int iy0 = min(max(ify, 0), GH - 1);
        int iy1 = min(max(ify + 1, 0), GH - 1);
        float wy0f = 1.0f - by, wy1f = by;

        const float* gp = gbase + (size_t)(2 * c2) * 2048 + z * 256 + 4 * xq4;
        float4 a0 = *reinterpret_cast<const float4*>(gp + iy0 * 16);
        float4 b0 = *reinterpret_cast<const float4*>(gp + iy1 * 16);
        float4 a1 = *reinterpret_cast<const float4*>(gp + 2048 + iy0 * 16);
        float4 b1 = *reinterpret_cast<const float4*>(gp + 2048 + iy1 * 16);

        float vA[4] = { a0.x * wy0f + b0.x * wy1f,   // ch 2c2, x=4xq4+0..3
                        a0.y * wy0f + b0.y * wy1f,
                        a0.z * wy0f + b0.z * wy1f,
                        a0.w * wy0f + b0.w * wy1f };
        float vB[4] = { a1.x * wy0f + b1.x * wy1f,   // ch 2c2+1
                        a1.y * wy0f + b1.y * wy1f,
                        a1.z * wy0f + b1.z * wy1f,
                        a1.w * wy0f + b1.w * wy1f };

        __half* dst = yb + r * YROW + z * YSLAB + (4 * xq4) * ENTRY + 2 * c2;
        #pragma unroll
        for (int i = 0; i < 4; ++i)
            *reinterpret_cast<__half2*>(dst + i * ENTRY) =
                __floats2half2_rn(vA[i], vB[i]);
    }
    __syncthreads();   // the ONLY barrier

    // ---- Phase 3: 2 px/thread, both rows, barrier-free ----
    float tx = (x0 + 0.5f) * (1.0f / 64.0f) - 0.5f;
    float fx = floorf(tx);
    int  ifx = (int)fx;
    float bx0 = tx - fx;
    bool edge = (ifx < 0 || ifx >= GW - 1);
    float w1a = edge ? 0.0f : bx0;
    float w1b = edge ? 0.0f : bx0 + (1.0f / 64.0f);
    const int xoff = min(max(ifx, 0), GW - 1) * ENTRY;

    float* ob = out + (size_t)n * C * HW + x0;

    #pragma unroll
    for (int j = 0; j < RPB; ++j) {
        const int row = row0 + j;
        const __half* rbuf = yb + j * YROW;
        float2 gz = j ? gzb : gza;

        __half2 vz0[6], vz1[6];
        #pragma unroll
        for (int p = 0; p < 2; ++p) {
            float tz = (p ? gz.y : gz.x) * 8.0f - 0.5f;
            float fz = floorf(tz);
            float bz = tz - fz;
            int ifz = (int)fz;
            int iz0 = min(max(ifz, 0), GD - 1);
            int iz1 = min(max(ifz + 1, 0), GD - 1);
            float w1 = p ? w1b : w1a;
            __half2 wx1 = __float2half2_rn(w1);
            __half2 wx0 = __float2half2_rn(1.0f - w1);
            __half2 wz0h = __float2half2_rn(1.0f - bz);
            __half2 wz1h = __float2half2_rn(bz);

            __half2 r0[6], r1[6];
            fetch_xlerp(rbuf, iz0 * YSLAB + xoff, wx0, wx1, r0);
            fetch_xlerp(rbuf, iz1 * YSLAB + xoff, wx0, wx1, r1);
            __half2* vz = p ? vz1 : vz0;
            #pragma unroll
            for (int kk = 0; kk < 6; ++kk)
                vz[kk] = __hfma2(r1[kk], wz1h, __hmul2(r0[kk], wz0h));
        }

        float* obr = ob + (size_t)row * W;
        #pragma unroll
        for (int kk = 0; kk < 6; ++kk) {
            float2 fa = __half22float2(vz0[kk]);   // (ch 2k,2k+1) px0
            float2 fb = __half22float2(vz1[kk]);   // (ch 2k,2k+1) px1
            float2 lo = make_float2(fa.x, fb.x);
            float2 hi = make_float2(fa.y, fb.y);
            __stcs(reinterpret_cast<float2*>(obr + (size_t)(2 * kk) * HW), lo);
            __stcs(reinterpret_cast<float2*>(obr + (size_t)(2 * kk + 1) * HW), hi);
        }
    }
}

extern "C" void kernel_launch(void* const* d_in, const int* in_sizes, int n_in,
                              void* d_out, int out_size) {
    const float* grid  = (const float*)d_in[0];   // (4,12,8,16,16) f32
    const float* guide = (const float*)d_in[1];   // (4,1,1024,1024) f32
    float* out = (float*)d_out;                   // (4,12,1024,1024) f32

    cudaFuncSetAttribute(slice_kernel,
                         cudaFuncAttributeMaxDynamicSharedMemorySize,
                         SMEM_BYTES);

    dim3 gridDim(H / RPB, Nb);                    // (512, 4) = 2048 blocks
    slice_kernel<<<gridDim, THREADS, SMEM_BYTES>>>(grid, guide, out);
}